// round 1
// baseline (speedup 1.0000x reference)
#include <cuda_runtime.h>
#include <math.h>

// Problem dims
#define Bb 32
#define Tt 64
#define Ee 512
#define Hh 1024
#define VTv 32000
#define HB (Hh*Bb)          // 32768
#define G4 (4*Hh)           // 4096

// ---------------- scratch (static device globals; no allocation) -------------
__device__ __align__(16) float g_srcX[Tt*HB];          // [T][H][B] projected src inputs
__device__ __align__(16) float g_tgtX[Tt*HB];          // [T][H][B]
__device__ __align__(16) float g_encHs[Tt*HB];         // [T][H][B] encoder top h
__device__ __align__(16) float g_h0e[2*HB];
__device__ __align__(16) float g_c0e[HB];
__device__ __align__(16) float g_c1e[HB];
__device__ __align__(16) float g_h0d[2*HB];
__device__ __align__(16) float g_h1d[2*HB];
__device__ __align__(16) float g_c0d[HB];
__device__ __align__(16) float g_c1d[HB];
__device__ __align__(16) float g_zero[HB];
__device__ __align__(16) float g_scoresT[Tt*Bb];
__device__ __align__(16) float g_attnT[Tt*Bb];
__device__ __align__(16) float g_ctxT[HB];
__device__ __align__(16) float g_wcPart[4*Hh*Bb];
__device__ __align__(16) float g_htT[HB];
__device__ __align__(16) float g_oePart[8*Ee*Bb];
__device__ __align__(16) float g_outemb[Tt*Bb*Ee];     // row-major [2048][512]
__device__ __align__(16) float g_Wre[2*2*Hh*G4];       // gate-interleaved enc weights
__device__ __align__(16) float g_Wrd[2*2*Hh*G4];
__device__ __align__(16) float g_bre[2*G4];
__device__ __align__(16) float g_brd[2*G4];
__device__ __align__(16) float g_logits[(size_t)Tt*Bb*VTv];  // 262MB

__device__ __forceinline__ float sigf(float x) { return 1.f/(1.f+expf(-x)); }

// ---------------- init ----------------
__global__ void zero_state() {
    int i = blockIdx.x*blockDim.x + threadIdx.x;
    if (i < HB) {
        g_zero[i]=0.f; g_c0e[i]=0.f; g_c1e[i]=0.f; g_c0d[i]=0.f; g_c1d[i]=0.f;
        g_h0e[i]=0.f; g_h0d[i]=0.f; g_h1d[i]=0.f;
    }
}

// Reorder W[l][2048][4096] (cols = g*1024+n) -> Wr[l][2048][n*4+g]; same for bias.
__global__ void reorder_W(const float* __restrict__ W, const float* __restrict__ b,
                          float* __restrict__ Wr, float* __restrict__ br) {
    long total = 2L*2*Hh*G4;   // 2 layers * 2048 rows * 4096 cols
    for (long i = (long)blockIdx.x*blockDim.x + threadIdx.x; i < total;
         i += (long)gridDim.x*blockDim.x) {
        long row = i >> 12;          // l*2048 + k
        int col = (int)(i & 4095);   // n*4 + g
        int n = col >> 2, g = col & 3;
        Wr[i] = W[(row<<12) + g*Hh + n];
    }
    int id = blockIdx.x*blockDim.x + threadIdx.x;
    if (id < 2*G4) {
        int l = id >> 12, col = id & 4095, n = col>>2, g = col&3;
        br[id] = b[(l<<12) + g*Hh + n];
    }
}

// ---------------- embedding + input projection ----------------
// out[t][n][b] = bias[n] + sum_k emb[tok(t,b)][k] * W[k][n]
__global__ void embed_proj(const int* __restrict__ tok /*[B][T]*/,
                           const float* __restrict__ emb,
                           const float4* __restrict__ W4 /*[512][256]*/,
                           const float4* __restrict__ b4,
                           float* __restrict__ outX /*[T][H][B]*/) {
    int t = blockIdx.y;
    int w = threadIdx.x >> 5, lane = threadIdx.x & 31;
    int n4 = blockIdx.x * 8 + w;                 // 0..255
    const float* ar = emb + (long)tok[lane*Tt + t] * Ee;
    float4 acc = b4[n4];
    #pragma unroll 4
    for (int k = 0; k < Ee; k++) {
        float a = ar[k];
        float4 wv = W4[k*(Hh/4) + n4];
        acc.x += a*wv.x; acc.y += a*wv.y; acc.z += a*wv.z; acc.w += a*wv.w;
    }
    float* o = outX + (long)t*HB + (n4*4)*Bb + lane;
    o[0]=acc.x; o[32]=acc.y; o[64]=acc.z; o[96]=acc.w;
}

// ---------------- fused LSTM cell step ----------------
// grid 128 x block 256 (8 warps): warp owns one n (0..1023), lane = b.
// Wr4[k][n] holds {W_i, W_j, W_f, W_o} for (k, n).
__global__ void lstm_step(const float* __restrict__ xT /*[1024][32]*/,
                          const float* __restrict__ hT /*[1024][32]*/,
                          float* __restrict__ c      /*[1024][32] in-place*/,
                          float* __restrict__ hOut   /*[1024][32]*/,
                          const float4* __restrict__ Wr4 /*[2048][1024]*/,
                          const float4* __restrict__ br4 /*[1024]*/) {
    int w = threadIdx.x >> 5, lane = threadIdx.x & 31;
    int n = blockIdx.x * 8 + w;
    float4 acc = make_float4(0.f,0.f,0.f,0.f);
    const float4* Wx = Wr4 + n;
    #pragma unroll 4
    for (int k = 0; k < Hh; k++) {
        float a = xT[k*Bb + lane];
        float4 wv = Wx[k*Hh];
        acc.x += a*wv.x; acc.y += a*wv.y; acc.z += a*wv.z; acc.w += a*wv.w;
    }
    const float4* Wh = Wr4 + (long)Hh*Hh + n;
    #pragma unroll 4
    for (int k = 0; k < Hh; k++) {
        float a = hT[k*Bb + lane];
        float4 wv = Wh[k*Hh];
        acc.x += a*wv.x; acc.y += a*wv.y; acc.z += a*wv.z; acc.w += a*wv.w;
    }
    float4 bb = br4[n];
    float zi = acc.x + bb.x, zj = acc.y + bb.y, zf = acc.z + bb.z, zo = acc.w + bb.w;
    int idx = n*Bb + lane;
    float cn = c[idx] * sigf(zf + 1.f) + sigf(zi) * tanhf(zj);
    c[idx] = cn;
    hOut[idx] = tanhf(cn) * sigf(zo);
}

// ---------------- attention ----------------
__global__ void attn_scores(const float* __restrict__ hT, const float* __restrict__ encHs,
                            float* __restrict__ scoresT) {
    int t = blockIdx.x;
    int w = threadIdx.x >> 5, lane = threadIdx.x & 31;   // block 128 = 4 warps
    const float* e = encHs + (long)t*HB;
    float s = 0.f;
    for (int h = w*256; h < w*256+256; h++) s += hT[h*Bb+lane]*e[h*Bb+lane];
    __shared__ float red[4][32];
    red[w][lane] = s; __syncthreads();
    if (w == 0)
        scoresT[t*Bb+lane] = red[0][lane]+red[1][lane]+red[2][lane]+red[3][lane];
}

__global__ void attn_softmax(const float* __restrict__ scoresT, float* __restrict__ attnT) {
    // block 1024 = 32 warps; warp = b, lane covers t and t+32
    int b = threadIdx.x >> 5, lane = threadIdx.x & 31;
    float s0 = scoresT[lane*Bb + b];
    float s1 = scoresT[(lane+32)*Bb + b];
    float m = fmaxf(s0, s1);
    #pragma unroll
    for (int o = 16; o; o >>= 1) m = fmaxf(m, __shfl_xor_sync(0xffffffffu, m, o));
    float e0 = expf(s0 - m), e1 = expf(s1 - m);
    float sum = e0 + e1;
    #pragma unroll
    for (int o = 16; o; o >>= 1) sum += __shfl_xor_sync(0xffffffffu, sum, o);
    float inv = 1.f/sum;
    attnT[lane*Bb + b] = e0*inv;
    attnT[(lane+32)*Bb + b] = e1*inv;
}

__global__ void attn_ctx(const float* __restrict__ attnT, const float* __restrict__ encHs,
                         float* __restrict__ ctxT) {
    int w = threadIdx.x >> 5, lane = threadIdx.x & 31;   // grid 128, block 256
    int h = blockIdx.x*8 + w;
    float s = 0.f;
    #pragma unroll 4
    for (int t = 0; t < Tt; t++)
        s += attnT[t*Bb+lane] * encHs[((long)t*Hh + h)*Bb + lane];
    ctxT[h*Bb+lane] = s;
}

// ---------------- small transposed GEMMs (warp-per-4-columns, split-K) ---------
// part[chunk][n][b] = sum_{k in chunk} A[k][b] * W[k][n],  A split as (A1 | A2) at K1.
__global__ void colgemm4(const float* __restrict__ A1, const float* __restrict__ A2, int K1,
                         int kchunk, const float4* __restrict__ W4, int N4,
                         float* __restrict__ part, int N) {
    int w = threadIdx.x >> 5, lane = threadIdx.x & 31;
    int n4 = blockIdx.x*8 + w;
    int kbeg = blockIdx.y * kchunk;
    const float* A = (kbeg < K1) ? A1 : (A2 - (long)K1*Bb);
    float4 acc = make_float4(0.f,0.f,0.f,0.f);
    #pragma unroll 4
    for (int k = kbeg; k < kbeg + kchunk; k++) {
        float a = A[(long)k*Bb + lane];
        float4 wv = W4[(long)k*N4 + n4];
        acc.x += a*wv.x; acc.y += a*wv.y; acc.z += a*wv.z; acc.w += a*wv.w;
    }
    float* p = part + (long)blockIdx.y*N*Bb + (n4*4)*Bb + lane;
    p[0]=acc.x; p[32]=acc.y; p[64]=acc.z; p[96]=acc.w;
}

__global__ void reduce_to_T(const float* __restrict__ part, int ksplit, int N,
                            const float* __restrict__ bias, float* __restrict__ outT) {
    int id = blockIdx.x*blockDim.x + threadIdx.x;
    if (id >= N*Bb) return;
    int n = id >> 5;
    float s = bias[n];
    for (int c = 0; c < ksplit; c++) s += part[(long)c*N*Bb + id];
    outT[id] = s;
}

__global__ void reduce_to_RM(const float* __restrict__ part, int ksplit, int N,
                             const float* __restrict__ bias, float* __restrict__ outRM,
                             int rowbase) {
    int id = blockIdx.x*blockDim.x + threadIdx.x;
    if (id >= N*Bb) return;
    int n = id >> 5, b = id & 31;
    float s = bias[n];
    for (int c = 0; c < ksplit; c++) s += part[(long)c*N*Bb + id];
    outRM[(long)(rowbase + b)*N + n] = s;
}

// ---------------- batched vocab GEMM ----------------
// C[2048][32000] = A[2048][512] @ Bw[512][32000] + bias
__global__ void gemm_logits(const float* __restrict__ A, const float* __restrict__ Bw,
                            const float* __restrict__ bias, float* __restrict__ C) {
    __shared__ float As[16][64];
    __shared__ float Bs[16][64];
    int tid = threadIdx.x;                 // 256 threads
    int bn = blockIdx.x * 64;
    int bm = blockIdx.y * 64;
    int tx = tid & 15, ty = tid >> 4;      // 16x16 thread grid, each 4x4 outputs
    int arow = tid >> 2, akq = tid & 3;    // A tile loaders
    int brow = tid >> 4, bcq = tid & 15;   // B tile loaders
    float acc[4][4] = {};
    for (int k0 = 0; k0 < 512; k0 += 16) {
        float4 av = *(const float4*)(A + (long)(bm+arow)*Ee + k0 + akq*4);
        As[akq*4+0][arow]=av.x; As[akq*4+1][arow]=av.y;
        As[akq*4+2][arow]=av.z; As[akq*4+3][arow]=av.w;
        float4 bv = *(const float4*)(Bw + (long)(k0+brow)*VTv + bn + bcq*4);
        Bs[brow][bcq*4+0]=bv.x; Bs[brow][bcq*4+1]=bv.y;
        Bs[brow][bcq*4+2]=bv.z; Bs[brow][bcq*4+3]=bv.w;
        __syncthreads();
        #pragma unroll
        for (int kk = 0; kk < 16; kk++) {
            float a0=As[kk][ty*4+0], a1=As[kk][ty*4+1], a2=As[kk][ty*4+2], a3=As[kk][ty*4+3];
            float b0=Bs[kk][tx*4+0], b1=Bs[kk][tx*4+1], b2=Bs[kk][tx*4+2], b3=Bs[kk][tx*4+3];
            acc[0][0]+=a0*b0; acc[0][1]+=a0*b1; acc[0][2]+=a0*b2; acc[0][3]+=a0*b3;
            acc[1][0]+=a1*b0; acc[1][1]+=a1*b1; acc[1][2]+=a1*b2; acc[1][3]+=a1*b3;
            acc[2][0]+=a2*b0; acc[2][1]+=a2*b1; acc[2][2]+=a2*b2; acc[2][3]+=a2*b3;
            acc[3][0]+=a3*b0; acc[3][1]+=a3*b1; acc[3][2]+=a3*b2; acc[3][3]+=a3*b3;
        }
        __syncthreads();
    }
    #pragma unroll
    for (int i = 0; i < 4; i++) {
        float* crow = C + (long)(bm+ty*4+i)*VTv + bn + tx*4;
        #pragma unroll
        for (int j = 0; j < 4; j++)
            crow[j] = acc[i][j] + bias[bn + tx*4 + j];
    }
}

// ---------------- final softmax over vocab, with layout remap -------------
// logits rows m = t*32 + b  ->  out rows (b*64 + t)
__global__ void softmax_rows(const float* __restrict__ logits, float* __restrict__ out) {
    int m = blockIdx.x;
    const float* lr = logits + (size_t)m*VTv;
    int tid = threadIdx.x;                 // 256
    __shared__ float red[256];
    float mx = -1e30f;
    for (int i = tid; i < VTv; i += 256) mx = fmaxf(mx, lr[i]);
    red[tid] = mx; __syncthreads();
    for (int s = 128; s; s >>= 1) { if (tid < s) red[tid] = fmaxf(red[tid], red[tid+s]); __syncthreads(); }
    mx = red[0]; __syncthreads();
    float sum = 0.f;
    for (int i = tid; i < VTv; i += 256) sum += expf(lr[i] - mx);
    red[tid] = sum; __syncthreads();
    for (int s = 128; s; s >>= 1) { if (tid < s) red[tid] += red[tid+s]; __syncthreads(); }
    sum = red[0];
    float inv = 1.f/sum;
    int t = m >> 5, b = m & 31;
    float* orow = out + (size_t)(b*Tt + t)*VTv;
    for (int i = tid; i < VTv; i += 256) orow[i] = expf(lr[i] - mx)*inv;
}

// ---------------- host ----------------
extern "C" void kernel_launch(void* const* d_in, const int* in_sizes, int n_in,
                              void* d_out, int out_size) {
    const int*   src    = (const int*)d_in[0];
    const int*   tgt    = (const int*)d_in[1];
    const float* s_emb  = (const float*)d_in[2];
    const float* s_pW   = (const float*)d_in[3];
    const float* s_pb   = (const float*)d_in[4];
    const float* t_emb  = (const float*)d_in[5];
    const float* t_pW   = (const float*)d_in[6];
    const float* t_pb   = (const float*)d_in[7];
    const float* enc_W  = (const float*)d_in[8];
    const float* enc_b  = (const float*)d_in[9];
    const float* dec_W  = (const float*)d_in[10];
    const float* dec_b  = (const float*)d_in[11];
    const float* W_c    = (const float*)d_in[12];
    const float* b_c    = (const float*)d_in[13];
    const float* proj_W = (const float*)d_in[14];
    const float* proj_b = (const float*)d_in[15];
    const float* proj_Wo= (const float*)d_in[16];
    const float* proj_bo= (const float*)d_in[17];
    float* out = (float*)d_out;

    float *srcX,*tgtX,*encHs,*h0e,*c0e,*c1e,*h0d,*h1d,*c0d,*c1d,*zero,
          *scoresT,*attnT,*ctxT,*wcPart,*htT,*oePart,*outemb,*Wre,*Wrd,*bre,*brd,*logits;
    cudaGetSymbolAddress((void**)&srcX,   g_srcX);
    cudaGetSymbolAddress((void**)&tgtX,   g_tgtX);
    cudaGetSymbolAddress((void**)&encHs,  g_encHs);
    cudaGetSymbolAddress((void**)&h0e,    g_h0e);
    cudaGetSymbolAddress((void**)&c0e,    g_c0e);
    cudaGetSymbolAddress((void**)&c1e,    g_c1e);
    cudaGetSymbolAddress((void**)&h0d,    g_h0d);
    cudaGetSymbolAddress((void**)&h1d,    g_h1d);
    cudaGetSymbolAddress((void**)&c0d,    g_c0d);
    cudaGetSymbolAddress((void**)&c1d,    g_c1d);
    cudaGetSymbolAddress((void**)&zero,   g_zero);
    cudaGetSymbolAddress((void**)&scoresT,g_scoresT);
    cudaGetSymbolAddress((void**)&attnT,  g_attnT);
    cudaGetSymbolAddress((void**)&ctxT,   g_ctxT);
    cudaGetSymbolAddress((void**)&wcPart, g_wcPart);
    cudaGetSymbolAddress((void**)&htT,    g_htT);
    cudaGetSymbolAddress((void**)&oePart, g_oePart);
    cudaGetSymbolAddress((void**)&outemb, g_outemb);
    cudaGetSymbolAddress((void**)&Wre,    g_Wre);
    cudaGetSymbolAddress((void**)&Wrd,    g_Wrd);
    cudaGetSymbolAddress((void**)&bre,    g_bre);
    cudaGetSymbolAddress((void**)&brd,    g_brd);
    cudaGetSymbolAddress((void**)&logits, g_logits);

    zero_state<<<(HB+255)/256, 256>>>();
    reorder_W<<<1024, 256>>>(enc_W, enc_b, Wre, bre);
    reorder_W<<<1024, 256>>>(dec_W, dec_b, Wrd, brd);
    embed_proj<<<dim3(32,64), 256>>>(src, s_emb, (const float4*)s_pW, (const float4*)s_pb, srcX);
    embed_proj<<<dim3(32,64), 256>>>(tgt, t_emb, (const float4*)t_pW, (const float4*)t_pb, tgtX);

    const float4* Wre4_l0 = (const float4*)Wre;
    const float4* Wre4_l1 = (const float4*)Wre + (long)2*Hh*Hh;   // layer stride 2048*4096 floats
    const float4* bre4_l0 = (const float4*)bre;
    const float4* bre4_l1 = (const float4*)bre + Hh;
    const float4* Wrd4_l0 = (const float4*)Wrd;
    const float4* Wrd4_l1 = (const float4*)Wrd + (long)2*Hh*Hh;
    const float4* brd4_l0 = (const float4*)brd;
    const float4* brd4_l1 = (const float4*)brd + Hh;

    // ---- encoder ----
    for (int t = 0; t < Tt; t++) {
        int p = t & 1;
        lstm_step<<<128,256>>>(srcX + (long)t*HB, h0e + p*HB, c0e, h0e + (1-p)*HB,
                               Wre4_l0, bre4_l0);
        const float* h1prev = t ? (encHs + (long)(t-1)*HB) : zero;
        lstm_step<<<128,256>>>(h0e + (1-p)*HB, h1prev, c1e, encHs + (long)t*HB,
                               Wre4_l1, bre4_l1);
    }

    // ---- decoder ----
    for (int t = 0; t < Tt; t++) {
        int p = t & 1;
        lstm_step<<<128,256>>>(tgtX + (long)t*HB, h0d + p*HB, c0d, h0d + (1-p)*HB,
                               Wrd4_l0, brd4_l0);
        lstm_step<<<128,256>>>(h0d + (1-p)*HB, h1d + p*HB, c1d, h1d + (1-p)*HB,
                               Wrd4_l1, brd4_l1);
        const float* hTop = h1d + (1-p)*HB;
        attn_scores<<<64,128>>>(hTop, encHs, scoresT);
        attn_softmax<<<1,1024>>>(scoresT, attnT);
        attn_ctx<<<128,256>>>(attnT, encHs, ctxT);
        // h_t = [h, ctx] @ W_c + b_c   (K=2048, N=1024, split-K=4)
        colgemm4<<<dim3(32,4),256>>>(hTop, ctxT, Hh, 512, (const float4*)W_c, Hh/4, wcPart, Hh);
        reduce_to_T<<<(Hh*Bb+255)/256,256>>>(wcPart, 4, Hh, b_c, htT);
        // outemb = h_t @ proj_W + proj_b  (K=1024, N=512, split-K=8)
        colgemm4<<<dim3(16,8),256>>>(htT, htT, Hh, 128, (const float4*)proj_W, Ee/4, oePart, Ee);
        reduce_to_RM<<<(Ee*Bb+255)/256,256>>>(oePart, 8, Ee, proj_b, outemb, t*Bb);
    }

    // ---- batched vocab projection + softmax ----
    gemm_logits<<<dim3(VTv/64, (Tt*Bb)/64), 256>>>(outemb, proj_Wo, proj_bo, logits);
    softmax_rows<<<Tt*Bb, 256>>>(logits, out);
}

// round 3
// speedup vs baseline: 2.4776x; 2.4776x over previous
#include <cuda_runtime.h>
#include <math.h>

#define Bb 32
#define Tt 64
#define Ee 512
#define Hh 1024
#define VTv 32000
#define HB (Hh*Bb)          // 32768
#define G4 (4*Hh)           // 4096
#define NBLK 128            // persistent grid size (<=148 SMs, all co-resident)

typedef unsigned long long u64;

__device__ __forceinline__ u64 pk2(float x, float y) {
    u64 r; asm("mov.b64 %0,{%1,%2};" : "=l"(r) : "f"(x), "f"(y)); return r;
}
__device__ __forceinline__ void fma2(u64 &d, u64 a, u64 b) {
    asm("fma.rn.f32x2 %0,%1,%2,%0;" : "+l"(d) : "l"(a), "l"(b));
}
__device__ __forceinline__ float2 up2(u64 v) {
    float2 f; asm("mov.b64 {%0,%1},%2;" : "=f"(f.x), "=f"(f.y) : "l"(v)); return f;
}
__device__ __forceinline__ float sigf(float x) { return 1.f/(1.f+expf(-x)); }

// ---------------- scratch ----------------
__device__ __align__(16) float g_srcX[Tt*HB];
__device__ __align__(16) float g_tgtX[Tt*HB];
__device__ __align__(16) float g_encHs[Tt*HB];
__device__ __align__(16) float g_h0e[2*HB];
__device__ __align__(16) float g_c0e[HB];
__device__ __align__(16) float g_c1e[HB];
__device__ __align__(16) float g_h0d[2*HB];
__device__ __align__(16) float g_h1d[2*HB];
__device__ __align__(16) float g_c0d[HB];
__device__ __align__(16) float g_c1d[HB];
__device__ __align__(16) float g_zero[HB];
__device__ __align__(16) float g_scoresT[Tt*Bb];
__device__ __align__(16) float g_attnT[Tt*Bb];
__device__ __align__(16) float g_ctxT[HB];
__device__ __align__(16) float g_wcPart[4*Hh*Bb];
__device__ __align__(16) float g_htT[HB];
__device__ __align__(16) float g_oePart[8*Ee*Bb];
__device__ __align__(16) float g_outemb[Tt*Bb*Ee];     // [2048][512] row-major
__device__ __align__(16) float g_Wre[2*2*Hh*G4];
__device__ __align__(16) float g_Wrd[2*2*Hh*G4];
__device__ __align__(16) float g_bre[2*G4];
__device__ __align__(16) float g_brd[2*G4];
__device__ __align__(16) float g_zxe[Tt*G4*Bb];
__device__ __align__(16) float g_zxd[Tt*G4*Bb];
__device__ __align__(16) float g_elog[(size_t)Tt*Bb*VTv]; // exp(logits), 262MB
__device__ unsigned g_bar;

// ---------------- init ----------------
__global__ void zero_state() {
    int i = blockIdx.x*blockDim.x + threadIdx.x;
    if (i == 0) g_bar = 0u;
    if (i < HB) {
        g_zero[i]=0.f; g_c0e[i]=0.f; g_c1e[i]=0.f; g_c0d[i]=0.f; g_c1d[i]=0.f;
        g_h0e[i]=0.f; g_h0e[i+HB]=0.f;
        g_h0d[i]=0.f; g_h0d[i+HB]=0.f;
        g_h1d[i]=0.f; g_h1d[i+HB]=0.f;
    }
}

// W[l][2048][4096] cols g*1024+n  ->  Wr[l][2048][n*4+g]
__global__ void reorder_W(const float* __restrict__ W, const float* __restrict__ b,
                          float* __restrict__ Wr, float* __restrict__ br) {
    long total = 2L*2*Hh*G4;
    for (long i = (long)blockIdx.x*blockDim.x + threadIdx.x; i < total;
         i += (long)gridDim.x*blockDim.x) {
        long row = i >> 12;
        int col = (int)(i & 4095);
        int n = col >> 2, g = col & 3;
        Wr[i] = W[(row<<12) + g*Hh + n];
    }
    int id = blockIdx.x*blockDim.x + threadIdx.x;
    if (id < 2*G4) {
        int l = id >> 12, col = id & 4095, n = col>>2, g = col&3;
        br[id] = b[(l<<12) + g*Hh + n];
    }
}

// ---------------- embedding + input projection ----------------
__global__ void embed_proj(const int* __restrict__ tok,
                           const float* __restrict__ emb,
                           const float4* __restrict__ W4,
                           const float4* __restrict__ b4,
                           float* __restrict__ outX) {
    int t = blockIdx.y;
    int w = threadIdx.x >> 5, lane = threadIdx.x & 31;
    int n4 = blockIdx.x * 8 + w;
    const float* ar = emb + (long)tok[lane*Tt + t] * Ee;
    float4 acc = b4[n4];
    #pragma unroll 4
    for (int k = 0; k < Ee; k++) {
        float a = ar[k];
        float4 wv = W4[k*(Hh/4) + n4];
        acc.x += a*wv.x; acc.y += a*wv.y; acc.z += a*wv.z; acc.w += a*wv.w;
    }
    float* o = outX + (long)t*HB + (n4*4)*Bb + lane;
    o[0]=acc.x; o[32]=acc.y; o[64]=acc.z; o[96]=acc.w;
}

// ---------------- shared tile MM core (f32x2, FMA-floor inner loop) ----------
// acc quad: 4 output cols (ncol0+wid*4 .. +3) x 32 b per warp.
__device__ __forceinline__ void mm_tiles(
    const float* __restrict__ XA, const float* __restrict__ XB, int K1,
    int kbeg, int kend, const float* __restrict__ W, int ldw, int ncol0,
    u64* As_d, float* Wt, u64 &acc0, u64 &acc1)
{
    int tid = threadIdx.x, lane = tid & 31, wid = tid >> 5;
    int kl = tid >> 3, sub = tid & 7;
    for (int k0 = kbeg; k0 < kend; k0 += 32) {
        int kr = k0 + kl;
        const float* X = (kr < K1) ? (XA + kr*Bb) : (XB + (long)(kr-K1)*Bb);
        float4 xv = *(const float4*)(X + sub*4);
        u64* ad = As_d + kl*32 + sub*4;
        ad[0]=pk2(xv.x,xv.x); ad[1]=pk2(xv.y,xv.y);
        ad[2]=pk2(xv.z,xv.z); ad[3]=pk2(xv.w,xv.w);
        *(float4*)(Wt + kl*36 + sub*4) = *(const float4*)(W + (long)kr*ldw + ncol0 + sub*4);
        __syncthreads();
        #pragma unroll
        for (int k = 0; k < 32; k++) {
            u64 aa = As_d[k*32 + lane];
            ulonglong2 w2 = *(const ulonglong2*)(Wt + k*36 + wid*4);
            fma2(acc0, aa, w2.x); fma2(acc1, aa, w2.y);
        }
        __syncthreads();
    }
}

// ---------------- precompute x-part LSTM gates for all timesteps -------------
__global__ void __launch_bounds__(256) xgate(const float* __restrict__ X,
                                             const float* __restrict__ W,
                                             float* __restrict__ out) {
    __shared__ __align__(16) u64 As_d[32*32];
    __shared__ __align__(16) float Wt[32*36];
    int t = blockIdx.y, bid = blockIdx.x;
    int lane = threadIdx.x & 31, wid = threadIdx.x >> 5;
    u64 a0 = 0ull, a1 = 0ull;
    mm_tiles(X + (long)t*HB, X, 2048, 0, 1024, W, 4096, bid*32, As_d, Wt, a0, a1);
    float2 v01 = up2(a0), v23 = up2(a1);
    float* p = out + (long)t*(G4*Bb) + (bid*32 + wid*4)*Bb + lane;
    p[0]=v01.x; p[32]=v01.y; p[64]=v23.x; p[96]=v23.y;
}

// ---------------- persistent sequence kernel ----------------
__device__ __forceinline__ void gbar(unsigned &tgt) {
    tgt += NBLK;
    __syncthreads();
    if (threadIdx.x == 0) {
        __threadfence();
        atomicAdd(&g_bar, 1u);
        unsigned v;
        do {
            asm volatile("ld.acquire.gpu.u32 %0,[%1];" : "=r"(v) : "l"(&g_bar) : "memory");
        } while (v < tgt);
        __threadfence();   // gpu-scope: invalidates L1D -> fresh reads below
    }
    __syncthreads();
}

__device__ __forceinline__ void lstm_epi(u64 a0, u64 a1, const float4* __restrict__ b4,
                                         const float* __restrict__ zx,
                                         float* __restrict__ c, float* __restrict__ h,
                                         int bid, int wid, int lane) {
    int n = bid*8 + wid;
    float2 g01 = up2(a0), g23 = up2(a1);
    float4 bb = b4[n];
    float zi = g01.x + bb.x, zj = g01.y + bb.y, zf = g23.x + bb.z, zo = g23.y + bb.w;
    if (zx) {
        const float* z = zx + n*128 + lane;
        zi += z[0]; zj += z[32]; zf += z[64]; zo += z[96];
    }
    int idx = n*Bb + lane;
    float cn = c[idx]*sigf(zf + 1.f) + sigf(zi)*tanhf(zj);
    c[idx] = cn;
    h[idx] = tanhf(cn)*sigf(zo);
}

__global__ void __launch_bounds__(256,1) seq_kernel(const float* __restrict__ W_c,
                                                    const float* __restrict__ b_c,
                                                    const float* __restrict__ proj_W,
                                                    const float* __restrict__ proj_b) {
    __shared__ __align__(16) u64 As_d[32*32];
    __shared__ __align__(16) float Wt[32*36];
    __shared__ float red[8*32];
    int tid = threadIdx.x, lane = tid & 31, wid = tid >> 5, bid = blockIdx.x;
    unsigned tgt = 0;

    const float* We0h = g_Wre + (long)1024*4096;
    const float* We1  = g_Wre + (long)2048*4096;
    const float* Wd0h = g_Wrd + (long)1024*4096;
    const float* Wd1  = g_Wrd + (long)2048*4096;
    const float4* be0 = (const float4*)g_bre;
    const float4* be1 = (const float4*)g_bre + Hh;
    const float4* bd0 = (const float4*)g_brd;
    const float4* bd1 = (const float4*)g_brd + Hh;

    // ---- encoder ----
    for (int t = 0; t < Tt; t++) {
        int p = t & 1;
        const float* h0prev = g_h0e + p*HB;
        float* h0cur = g_h0e + (1-p)*HB;
        {
            u64 a0=0ull, a1=0ull;
            mm_tiles(h0prev, h0prev, 2048, 0, 1024, We0h, 4096, bid*32, As_d, Wt, a0, a1);
            lstm_epi(a0, a1, be0, g_zxe + (long)t*(G4*Bb), g_c0e, h0cur, bid, wid, lane);
        }
        gbar(tgt);
        const float* h1prev = t ? (g_encHs + (long)(t-1)*HB) : g_zero;
        {
            u64 a0=0ull, a1=0ull;
            mm_tiles(h0cur, h1prev, 1024, 0, 2048, We1, 4096, bid*32, As_d, Wt, a0, a1);
            lstm_epi(a0, a1, be1, nullptr, g_c1e, g_encHs + (long)t*HB, bid, wid, lane);
        }
        gbar(tgt);
    }

    // ---- decoder ----
    for (int t = 0; t < Tt; t++) {
        int p = t & 1;
        const float* h0prev = g_h0d + p*HB;
        float* h0cur = g_h0d + (1-p)*HB;
        const float* h1prev = g_h1d + p*HB;
        float* h1cur = g_h1d + (1-p)*HB;
        {
            u64 a0=0ull, a1=0ull;
            mm_tiles(h0prev, h0prev, 2048, 0, 1024, Wd0h, 4096, bid*32, As_d, Wt, a0, a1);
            lstm_epi(a0, a1, bd0, g_zxd + (long)t*(G4*Bb), g_c0d, h0cur, bid, wid, lane);
        }
        gbar(tgt);
        {
            u64 a0=0ull, a1=0ull;
            mm_tiles(h0cur, h1prev, 1024, 0, 2048, Wd1, 4096, bid*32, As_d, Wt, a0, a1);
            lstm_epi(a0, a1, bd1, nullptr, g_c1d, h1cur, bid, wid, lane);
        }
        gbar(tgt);

        // scores[t'][b] = <h1cur, encHs[t']>
        if (bid < 64) {
            const float* e = g_encHs + (long)bid*HB;
            float s = 0.f;
            #pragma unroll 4
            for (int h = wid*128; h < wid*128 + 128; h++)
                s += h1cur[h*Bb + lane] * e[h*Bb + lane];
            red[wid*32 + lane] = s;
            __syncthreads();
            if (wid == 0) {
                float acc = 0.f;
                #pragma unroll
                for (int j = 0; j < 8; j++) acc += red[j*32 + lane];
                g_scoresT[bid*Bb + lane] = acc;
            }
            __syncthreads();
        }
        gbar(tgt);

        // softmax over t' (block 0, warp 0; lane = b)
        if (bid == 0 && tid < 32) {
            float sc[Tt];
            float mx = -1e30f;
            #pragma unroll
            for (int q = 0; q < Tt; q++) { sc[q] = g_scoresT[q*Bb + tid]; mx = fmaxf(mx, sc[q]); }
            float sum = 0.f;
            #pragma unroll
            for (int q = 0; q < Tt; q++) { sc[q] = expf(sc[q] - mx); sum += sc[q]; }
            float inv = 1.f/sum;
            #pragma unroll
            for (int q = 0; q < Tt; q++) g_attnT[q*Bb + tid] = sc[q]*inv;
        }
        gbar(tgt);

        // ctx[h][b]
        {
            int h = bid*8 + wid;
            float s = 0.f;
            #pragma unroll 8
            for (int q = 0; q < Tt; q++)
                s += g_attnT[q*Bb + lane] * g_encHs[((long)q*Hh + h)*Bb + lane];
            g_ctxT[h*Bb + lane] = s;
        }
        gbar(tgt);

        // W_c partial: [h1cur|ctx] @ W_c   (nt 0..31, ks 0..3)
        {
            u64 a0=0ull, a1=0ull;
            int nt = bid >> 2, ks = bid & 3;
            mm_tiles(h1cur, g_ctxT, 1024, ks*512, ks*512 + 512, W_c, 1024, nt*32,
                     As_d, Wt, a0, a1);
            float2 v01 = up2(a0), v23 = up2(a1);
            float* gp = g_wcPart + ks*HB + (nt*32 + wid*4)*Bb + lane;
            gp[0]=v01.x; gp[32]=v01.y; gp[64]=v23.x; gp[96]=v23.y;
        }
        gbar(tgt);

        // reduce -> htT
        {
            int id = bid*256 + tid;   // 32768
            int n = id >> 5;
            g_htT[id] = b_c[n] + g_wcPart[id] + g_wcPart[HB + id]
                      + g_wcPart[2*HB + id] + g_wcPart[3*HB + id];
        }
        gbar(tgt);

        // proj partial: htT @ proj_W  (nt 0..15, ks 0..7)
        {
            u64 a0=0ull, a1=0ull;
            int nt = bid >> 3, ks = bid & 7;
            mm_tiles(g_htT, g_htT, 2048, ks*128, ks*128 + 128, proj_W, 512, nt*32,
                     As_d, Wt, a0, a1);
            float2 v01 = up2(a0), v23 = up2(a1);
            float* gp = g_oePart + ks*(Ee*Bb) + (nt*32 + wid*4)*Bb + lane;
            gp[0]=v01.x; gp[32]=v01.y; gp[64]=v23.x; gp[96]=v23.y;
        }
        gbar(tgt);

        // reduce -> outemb row-major [t*32+b][512]
        if (bid < 64) {
            int id = bid*256 + tid;   // 16384
            int n = id >> 5, b = id & 31;
            float s = proj_b[n];
            #pragma unroll
            for (int s8 = 0; s8 < 8; s8++) s += g_oePart[s8*(Ee*Bb) + id];
            g_outemb[((long)t*Bb + b)*Ee + n] = s;
        }
        gbar(tgt);
    }
}

// ---------------- vocab GEMM with exp() epilogue ----------------
// E[2048][32000] = exp(A[2048][512] @ Bw[512][32000] + bias)
__global__ void __launch_bounds__(256) gemm_logits(const float* __restrict__ A,
                                                   const float* __restrict__ Bw,
                                                   const float* __restrict__ bias,
                                                   float* __restrict__ E) {
    __shared__ float As[16][64];
    __shared__ float Bs[16][64];
    int tid = threadIdx.x;
    int bn = blockIdx.x * 64;
    int bm = blockIdx.y * 64;
    int tx = tid & 15, ty = tid >> 4;
    int arow = tid >> 2, akq = tid & 3;
    int brow = tid >> 4, bcq = tid & 15;
    u64 acc2[4][2] = {};
    for (int k0 = 0; k0 < 512; k0 += 16) {
        float4 av = *(const float4*)(A + (long)(bm+arow)*Ee + k0 + akq*4);
        As[akq*4+0][arow]=av.x; As[akq*4+1][arow]=av.y;
        As[akq*4+2][arow]=av.z; As[akq*4+3][arow]=av.w;
        float4 bv = *(const float4*)(Bw + (long)(k0+brow)*VTv + bn + bcq*4);
        *(float4*)&Bs[brow][bcq*4] = bv;
        __syncthreads();
        #pragma unroll
        for (int kk = 0; kk < 16; kk++) {
            float4 a4 = *(const float4*)&As[kk][ty*4];
            ulonglong2 b2 = *(const ulonglong2*)&Bs[kk][tx*4];
            u64 aa;
            aa = pk2(a4.x, a4.x); fma2(acc2[0][0], aa, b2.x); fma2(acc2[0][1], aa, b2.y);
            aa = pk2(a4.y, a4.y); fma2(acc2[1][0], aa, b2.x); fma2(acc2[1][1], aa, b2.y);
            aa = pk2(a4.z, a4.z); fma2(acc2[2][0], aa, b2.x); fma2(acc2[2][1], aa, b2.y);
            aa = pk2(a4.w, a4.w); fma2(acc2[3][0], aa, b2.x); fma2(acc2[3][1], aa, b2.y);
        }
        __syncthreads();
    }
    #pragma unroll
    for (int i = 0; i < 4; i++) {
        float* erow = E + (size_t)(bm+ty*4+i)*VTv + bn + tx*4;
        float2 c01 = up2(acc2[i][0]), c23 = up2(acc2[i][1]);
        erow[0] = expf(c01.x + bias[bn+tx*4+0]);
        erow[1] = expf(c01.y + bias[bn+tx*4+1]);
        erow[2] = expf(c23.x + bias[bn+tx*4+2]);
        erow[3] = expf(c23.y + bias[bn+tx*4+3]);
    }
}

// ---------------- normalize + layout remap ----------------
__global__ void softmax_norm(const float* __restrict__ E, float* __restrict__ out) {
    int m = blockIdx.x;                      // m = t*32 + b
    const float* er = E + (size_t)m*VTv;
    int tid = threadIdx.x;                   // 256
    __shared__ float red[256];
    float sum = 0.f;
    for (int i = tid; i < VTv; i += 256) sum += er[i];
    red[tid] = sum; __syncthreads();
    for (int s = 128; s; s >>= 1) { if (tid < s) red[tid] += red[tid+s]; __syncthreads(); }
    float inv = 1.f/red[0];
    int t = m >> 5, b = m & 31;
    float* orow = out + (size_t)(b*Tt + t)*VTv;
    for (int i = tid; i < VTv; i += 256) orow[i] = er[i]*inv;
}

// ---------------- host ----------------
extern "C" void kernel_launch(void* const* d_in, const int* in_sizes, int n_in,
                              void* d_out, int out_size) {
    const int*   src    = (const int*)d_in[0];
    const int*   tgt    = (const int*)d_in[1];
    const float* s_emb  = (const float*)d_in[2];
    const float* s_pW   = (const float*)d_in[3];
    const float* s_pb   = (const float*)d_in[4];
    const float* t_emb  = (const float*)d_in[5];
    const float* t_pW   = (const float*)d_in[6];
    const float* t_pb   = (const float*)d_in[7];
    const float* enc_W  = (const float*)d_in[8];
    const float* enc_b  = (const float*)d_in[9];
    const float* dec_W  = (const float*)d_in[10];
    const float* dec_b  = (const float*)d_in[11];
    const float* W_c    = (const float*)d_in[12];
    const float* b_c    = (const float*)d_in[13];
    const float* proj_W = (const float*)d_in[14];
    const float* proj_b = (const float*)d_in[15];
    const float* proj_Wo= (const float*)d_in[16];
    const float* proj_bo= (const float*)d_in[17];
    float* out = (float*)d_out;

    float *srcX,*tgtX,*Wre,*Wrd,*zxe,*zxd,*outemb,*elog;
    cudaGetSymbolAddress((void**)&srcX,   g_srcX);
    cudaGetSymbolAddress((void**)&tgtX,   g_tgtX);
    cudaGetSymbolAddress((void**)&Wre,    g_Wre);
    cudaGetSymbolAddress((void**)&Wrd,    g_Wrd);
    cudaGetSymbolAddress((void**)&zxe,    g_zxe);
    cudaGetSymbolAddress((void**)&zxd,    g_zxd);
    cudaGetSymbolAddress((void**)&outemb, g_outemb);
    cudaGetSymbolAddress((void**)&elog,   g_elog);
    float *bre, *brd;
    cudaGetSymbolAddress((void**)&bre,    g_bre);
    cudaGetSymbolAddress((void**)&brd,    g_brd);

    zero_state<<<(HB+255)/256, 256>>>();
    reorder_W<<<1024, 256>>>(enc_W, enc_b, Wre, bre);
    reorder_W<<<1024, 256>>>(dec_W, dec_b, Wrd, brd);
    embed_proj<<<dim3(32,64), 256>>>(src, s_emb, (const float4*)s_pW, (const float4*)s_pb, srcX);
    embed_proj<<<dim3(32,64), 256>>>(tgt, t_emb, (const float4*)t_pW, (const float4*)t_pb, tgtX);

    // x-part gate pre-activations for all timesteps (layer 0 of each stack)
    xgate<<<dim3(NBLK,Tt), 256>>>(srcX, Wre, zxe);
    xgate<<<dim3(NBLK,Tt), 256>>>(tgtX, Wrd, zxd);

    // full recurrent encoder+decoder in one persistent kernel
    seq_kernel<<<NBLK, 256>>>(W_c, b_c, proj_W, proj_b);

    // vocab projection (+exp) and normalization
    gemm_logits<<<dim3(VTv/64, (Tt*Bb)/64), 256>>>(outemb, proj_Wo, proj_bo, elog);
    softmax_norm<<<Tt*Bb, 256>>>(elog, out);
}

// round 4
// speedup vs baseline: 5.4843x; 2.2135x over previous
#include <cuda_runtime.h>
#include <math.h>

#define Bb 32
#define Tt 64
#define Ee 512
#define Hh 1024
#define VTv 32000
#define HB (Hh*Bb)          // 32768
#define G4 (4*Hh)           // 4096
#define NBLK 128
#define KT 64

typedef unsigned long long u64;

__device__ __forceinline__ u64 pk2(float x, float y) {
    u64 r; asm("mov.b64 %0,{%1,%2};" : "=l"(r) : "f"(x), "f"(y)); return r;
}
__device__ __forceinline__ void fma2(u64 &d, u64 a, u64 b) {
    asm("fma.rn.f32x2 %0,%1,%2,%0;" : "+l"(d) : "l"(a), "l"(b));
}
__device__ __forceinline__ float2 up2(u64 v) {
    float2 f; asm("mov.b64 {%0,%1},%2;" : "=f"(f.x), "=f"(f.y) : "l"(v)); return f;
}
__device__ __forceinline__ float sigf(float x) { return 1.f/(1.f+expf(-x)); }

// ---------------- scratch ----------------
__device__ __align__(16) float g_srcX[Tt*HB];
__device__ __align__(16) float g_tgtX[Tt*HB];
__device__ __align__(16) float g_encHs[Tt*HB];
__device__ __align__(16) float g_h0e[2*HB];
__device__ __align__(16) float g_c0e[HB];
__device__ __align__(16) float g_c1e[HB];
__device__ __align__(16) float g_h0d[2*HB];
__device__ __align__(16) float g_h1d[2*HB];
__device__ __align__(16) float g_c0d[HB];
__device__ __align__(16) float g_c1d[HB];
__device__ __align__(16) float g_zero[HB];
__device__ __align__(16) float g_scoresT[Tt*Bb];
__device__ __align__(16) float g_ctxT[HB];
__device__ __align__(16) float g_wcPart[4*Hh*Bb];
__device__ __align__(16) float g_htT[HB];
__device__ __align__(16) float g_oePart[8*Ee*Bb];
__device__ __align__(16) float g_outemb[Tt*Bb*Ee];     // [2048][512] row-major
__device__ __align__(16) float g_Wre[2*2*Hh*G4];
__device__ __align__(16) float g_Wrd[2*2*Hh*G4];
__device__ __align__(16) float g_bre[2*G4];
__device__ __align__(16) float g_brd[2*G4];
__device__ __align__(16) float g_zxe[Tt*G4*Bb];
__device__ __align__(16) float g_zxd[Tt*G4*Bb];
__device__ __align__(16) float g_elog[(size_t)Tt*Bb*VTv]; // exp(logits)
__device__ unsigned g_bar;

// dynamic smem layout (seq_kernel / xgate):
//  As : u64  [2*KT*32]   0     .. 32768
//  Ws : float[2*KT*32]   32768 .. 49152
//  red: float[4*32*33]   49152 .. 66048
//  attw:float[64*33]     66048 .. 74496
#define SMEM_SEQ 74496
#define SMEM_XG  66048

// ---------------- init ----------------
__global__ void zero_state() {
    int i = blockIdx.x*blockDim.x + threadIdx.x;
    if (i == 0) g_bar = 0u;
    if (i < HB) {
        g_zero[i]=0.f; g_c0e[i]=0.f; g_c1e[i]=0.f; g_c0d[i]=0.f; g_c1d[i]=0.f;
        g_h0e[i]=0.f; g_h0e[i+HB]=0.f;
        g_h0d[i]=0.f; g_h0d[i+HB]=0.f;
        g_h1d[i]=0.f; g_h1d[i+HB]=0.f;
    }
}

// W[l][2048][4096] cols g*1024+n  ->  Wr[l][2048][n*4+g]
__global__ void reorder_W(const float* __restrict__ W, const float* __restrict__ b,
                          float* __restrict__ Wr, float* __restrict__ br) {
    long total = 2L*2*Hh*G4;
    for (long i = (long)blockIdx.x*blockDim.x + threadIdx.x; i < total;
         i += (long)gridDim.x*blockDim.x) {
        long row = i >> 12;
        int col = (int)(i & 4095);
        int n = col >> 2, g = col & 3;
        Wr[i] = W[(row<<12) + g*Hh + n];
    }
    int id = blockIdx.x*blockDim.x + threadIdx.x;
    if (id < 2*G4) {
        int l = id >> 12, col = id & 4095, n = col>>2, g = col&3;
        br[id] = b[(l<<12) + g*Hh + n];
    }
}

// ---------------- embedding + input projection ----------------
__global__ void embed_proj(const int* __restrict__ tok,
                           const float* __restrict__ emb,
                           const float4* __restrict__ W4,
                           const float4* __restrict__ b4,
                           float* __restrict__ outX) {
    int t = blockIdx.y;
    int w = threadIdx.x >> 5, lane = threadIdx.x & 31;
    int n4 = blockIdx.x * 8 + w;
    const float* ar = emb + (long)tok[lane*Tt + t] * Ee;
    float4 acc = b4[n4];
    #pragma unroll 4
    for (int k = 0; k < Ee; k++) {
        float a = ar[k];
        float4 wv = W4[k*(Hh/4) + n4];
        acc.x += a*wv.x; acc.y += a*wv.y; acc.z += a*wv.z; acc.w += a*wv.w;
    }
    float* o = outX + (long)t*HB + (n4*4)*Bb + lane;
    o[0]=acc.x; o[32]=acc.y; o[64]=acc.z; o[96]=acc.w;
}

// ---------------- double-buffered high-density tile GEMM ----------------
// Block (256 thr, 8 warps = 2 colgroups x 4 ksplit) computes, into red[4][32][33]:
//   partial[ks][c][b] = sum_{k in ks-slice} X[k][b] * W[k][ncol0+c]
// over k in [kbeg,kend) (multiple of KT). X = XA for k<K1 else XB[k-K1].
__device__ __forceinline__ void stage_mm(
    const float* __restrict__ XA, const float* __restrict__ XB, int K1,
    int kbeg, int kend, const float* __restrict__ W, int ldw, int ncol0,
    u64* As, float* Ws, float* red)
{
    int tid = threadIdx.x, lane = tid & 31, wid = tid >> 5;
    int cg = wid >> 2, ks = wid & 3;
    int r0 = tid >> 3, c4 = (tid & 7) * 4;
    u64 acc[8] = {};
    int nt = (kend - kbeg) >> 6;
    float4 pa0, pa1, pw0, pw1;
    {
        int ka = kbeg + r0, kb = kbeg + r0 + 32;
        const float* Xp = (ka < K1) ? XA + ka*Bb : XB + (long)(ka-K1)*Bb;
        const float* Xq = (kb < K1) ? XA + kb*Bb : XB + (long)(kb-K1)*Bb;
        pa0 = *(const float4*)(Xp + c4);
        pa1 = *(const float4*)(Xq + c4);
        pw0 = *(const float4*)(W + (long)ka*ldw + ncol0 + c4);
        pw1 = *(const float4*)(W + (long)kb*ldw + ncol0 + c4);
    }
    for (int it = 0; it < nt; it++) {
        int buf = it & 1;
        u64* Ab = As + buf*KT*32;
        float* Wb = Ws + buf*KT*32;
        {
            u64* A0 = Ab + r0*32 + c4;
            ulonglong2 q;
            q.x = pk2(pa0.x,pa0.x); q.y = pk2(pa0.y,pa0.y); *(ulonglong2*)A0 = q;
            q.x = pk2(pa0.z,pa0.z); q.y = pk2(pa0.w,pa0.w); *(ulonglong2*)(A0+2) = q;
            u64* A1 = Ab + (r0+32)*32 + c4;
            q.x = pk2(pa1.x,pa1.x); q.y = pk2(pa1.y,pa1.y); *(ulonglong2*)A1 = q;
            q.x = pk2(pa1.z,pa1.z); q.y = pk2(pa1.w,pa1.w); *(ulonglong2*)(A1+2) = q;
            *(float4*)(Wb + r0*32 + c4) = pw0;
            *(float4*)(Wb + (r0+32)*32 + c4) = pw1;
        }
        __syncthreads();
        if (it + 1 < nt) {
            int k0 = kbeg + (it+1)*KT;
            int ka = k0 + r0, kb = k0 + r0 + 32;
            const float* Xp = (ka < K1) ? XA + ka*Bb : XB + (long)(ka-K1)*Bb;
            const float* Xq = (kb < K1) ? XA + kb*Bb : XB + (long)(kb-K1)*Bb;
            pa0 = *(const float4*)(Xp + c4);
            pa1 = *(const float4*)(Xq + c4);
            pw0 = *(const float4*)(W + (long)ka*ldw + ncol0 + c4);
            pw1 = *(const float4*)(W + (long)kb*ldw + ncol0 + c4);
        }
        int kb0 = ks * 16;
        #pragma unroll
        for (int kk = 0; kk < 16; kk++) {
            u64 aa = Ab[(kb0+kk)*32 + lane];
            const float* wr = Wb + (kb0+kk)*32 + cg*16;
            ulonglong2 w0 = *(const ulonglong2*)wr;
            ulonglong2 w1 = *(const ulonglong2*)(wr+4);
            ulonglong2 w2 = *(const ulonglong2*)(wr+8);
            ulonglong2 w3 = *(const ulonglong2*)(wr+12);
            fma2(acc[0], aa, w0.x); fma2(acc[1], aa, w0.y);
            fma2(acc[2], aa, w1.x); fma2(acc[3], aa, w1.y);
            fma2(acc[4], aa, w2.x); fma2(acc[5], aa, w2.y);
            fma2(acc[6], aa, w3.x); fma2(acc[7], aa, w3.y);
        }
        __syncthreads();
    }
    #pragma unroll
    for (int a = 0; a < 8; a++) {
        float2 v = up2(acc[a]);
        red[(ks*32 + cg*16 + 2*a)*33 + lane]     = v.x;
        red[(ks*32 + cg*16 + 2*a + 1)*33 + lane] = v.y;
    }
    __syncthreads();
}

// reduce 4 ksplits, apply LSTM cell (block covers n = bid*8 .. +8)
__device__ __forceinline__ void lstm_epi2(const float* red, const float4* __restrict__ b4,
                                          const float* __restrict__ zx,
                                          float* __restrict__ c, float* __restrict__ h,
                                          int bid) {
    int tid = threadIdx.x, lane = tid & 31, n8 = tid >> 5;
    int n = bid*8 + n8;
    float zi=0.f, zj=0.f, zf=0.f, zo=0.f;
    #pragma unroll
    for (int s = 0; s < 4; s++) {
        const float* r = red + (s*32 + n8*4)*33 + lane;
        zi += r[0]; zj += r[33]; zf += r[66]; zo += r[99];
    }
    float4 bb = b4[n];
    zi += bb.x; zj += bb.y; zf += bb.z; zo += bb.w;
    if (zx) {
        const float* z = zx + n*128 + lane;
        zi += z[0]; zj += z[32]; zf += z[64]; zo += z[96];
    }
    int idx = n*Bb + lane;
    float cn = c[idx]*sigf(zf + 1.f) + sigf(zi)*tanhf(zj);
    c[idx] = cn;
    h[idx] = tanhf(cn)*sigf(zo);
}

// reduce 4 ksplits to dst[c*32+b] (32 cols x 32 b)
__device__ __forceinline__ void part_epi(const float* red, float* __restrict__ dst) {
    for (int i = threadIdx.x; i < 32*32; i += 256) {
        int cl = i >> 5, b = i & 31;
        float s = red[cl*33 + b] + red[(32+cl)*33 + b]
                + red[(64+cl)*33 + b] + red[(96+cl)*33 + b];
        dst[cl*32 + b] = s;
    }
}

// ---------------- xgate precompute (parallel over t) ----------------
__global__ void __launch_bounds__(256) xgate(const float* __restrict__ X,
                                             const float* __restrict__ W,
                                             float* __restrict__ out) {
    extern __shared__ __align__(16) unsigned char dynsmem[];
    u64* As = (u64*)dynsmem;
    float* Ws = (float*)(dynsmem + 32768);
    float* red = (float*)(dynsmem + 49152);
    int t = blockIdx.y, ncol0 = blockIdx.x * 32;
    stage_mm(X + (long)t*HB, X + (long)t*HB, 1<<30, 0, 1024, W, 4096, ncol0,
             As, Ws, red);
    part_epi(red, out + (long)t*(G4*Bb) + ncol0*32);
}

// ---------------- global barrier ----------------
__device__ __forceinline__ void gbar(unsigned &tgt) {
    tgt += NBLK;
    __threadfence();
    __syncthreads();
    if (threadIdx.x == 0) {
        atomicAdd(&g_bar, 1u);
        unsigned v;
        do {
            asm volatile("ld.acquire.gpu.u32 %0,[%1];" : "=r"(v) : "l"(&g_bar) : "memory");
        } while (v < tgt);
        __threadfence();   // CCTL.IVALL: invalidates this SM's L1D for all warps
    }
    __syncthreads();
}

// ---------------- persistent sequence kernel ----------------
__global__ void __launch_bounds__(256,1) seq_kernel(const float* __restrict__ W_c,
                                                    const float* __restrict__ b_c,
                                                    const float* __restrict__ proj_W,
                                                    const float* __restrict__ proj_b) {
    extern __shared__ __align__(16) unsigned char dynsmem[];
    u64* As = (u64*)dynsmem;
    float* Ws = (float*)(dynsmem + 32768);
    float* red = (float*)(dynsmem + 49152);
    float* attw = (float*)(dynsmem + 66048);   // [64][33]
    int tid = threadIdx.x, lane = tid & 31, wid = tid >> 5, bid = blockIdx.x;
    unsigned tgt = 0;

    const float* We0h = g_Wre + (long)1024*4096;
    const float* We1  = g_Wre + (long)2048*4096;
    const float* Wd0h = g_Wrd + (long)1024*4096;
    const float* Wd1  = g_Wrd + (long)2048*4096;
    const float4* be0 = (const float4*)g_bre;
    const float4* be1 = (const float4*)g_bre + Hh;
    const float4* bd0 = (const float4*)g_brd;
    const float4* bd1 = (const float4*)g_brd + Hh;
    int ncol0 = bid * 32;

    // ---- encoder ----
    for (int t = 0; t < Tt; t++) {
        int p = t & 1;
        const float* h0prev = g_h0e + p*HB;
        float* h0cur = g_h0e + (1-p)*HB;
        stage_mm(h0prev, h0prev, 1<<30, 0, 1024, We0h, 4096, ncol0, As, Ws, red);
        lstm_epi2(red, be0, g_zxe + (long)t*(G4*Bb), g_c0e, h0cur, bid);
        gbar(tgt);
        const float* h1prev = t ? (g_encHs + (long)(t-1)*HB) : g_zero;
        stage_mm(h0cur, h1prev, 1024, 0, 2048, We1, 4096, ncol0, As, Ws, red);
        lstm_epi2(red, be1, nullptr, g_c1e, g_encHs + (long)t*HB, bid);
        gbar(tgt);
    }

    // ---- decoder ----
    for (int t = 0; t < Tt; t++) {
        int p = t & 1;
        const float* h0prev = g_h0d + p*HB;
        float* h0cur = g_h0d + (1-p)*HB;
        const float* h1prev = g_h1d + p*HB;
        float* h1cur = g_h1d + (1-p)*HB;

        stage_mm(h0prev, h0prev, 1<<30, 0, 1024, Wd0h, 4096, ncol0, As, Ws, red);
        lstm_epi2(red, bd0, g_zxd + (long)t*(G4*Bb), g_c0d, h0cur, bid);
        gbar(tgt);
        stage_mm(h0cur, h1prev, 1024, 0, 2048, Wd1, 4096, ncol0, As, Ws, red);
        lstm_epi2(red, bd1, nullptr, g_c1d, h1cur, bid);
        gbar(tgt);

        // scores[t'][b] = <h1cur, encHs[t']>   (blocks 0..63)
        if (bid < Tt) {
            const float* e = g_encHs + (long)bid*HB;
            float s = 0.f;
            #pragma unroll 4
            for (int hh = wid*128; hh < wid*128 + 128; hh++)
                s += h1cur[hh*Bb + lane] * e[hh*Bb + lane];
            attw[wid*33 + lane] = s;
            __syncthreads();
            if (wid == 0) {
                float a = 0.f;
                #pragma unroll
                for (int j = 0; j < 8; j++) a += attw[j*33 + lane];
                g_scoresT[bid*Bb + lane] = a;
            }
            __syncthreads();
        }
        gbar(tgt);

        // softmax (redundant per block, warp 0) + ctx
        if (wid == 0) {
            float mx = -1e30f;
            #pragma unroll
            for (int q = 0; q < Tt; q++) mx = fmaxf(mx, g_scoresT[q*Bb + lane]);
            float sum = 0.f;
            #pragma unroll
            for (int q = 0; q < Tt; q++) {
                float e = expf(g_scoresT[q*Bb + lane] - mx);
                attw[q*33 + lane] = e; sum += e;
            }
            float inv = 1.f/sum;
            #pragma unroll
            for (int q = 0; q < Tt; q++) attw[q*33 + lane] *= inv;
        }
        __syncthreads();
        {
            int hh = bid*8 + wid;
            float s = 0.f;
            #pragma unroll 8
            for (int q = 0; q < Tt; q++)
                s += attw[q*33 + lane] * g_encHs[((long)q*Hh + hh)*Bb + lane];
            g_ctxT[hh*Bb + lane] = s;
        }
        gbar(tgt);

        // W_c: 32 colblocks x 4 grid-ksplit
        {
            int nc = (bid >> 2) * 32, ksg = bid & 3;
            stage_mm(h1cur, g_ctxT, 1024, ksg*512, ksg*512 + 512, W_c, 1024, nc,
                     As, Ws, red);
            part_epi(red, g_wcPart + (long)ksg*HB + nc*32);
        }
        gbar(tgt);

        // reduce -> htT
        {
            int id = bid*256 + tid;
            int n = id >> 5;
            g_htT[id] = b_c[n] + g_wcPart[id] + g_wcPart[HB + id]
                      + g_wcPart[2*HB + id] + g_wcPart[3*HB + id];
        }
        gbar(tgt);

        // proj: 16 colblocks x 8 grid-ksplit
        {
            int nc = (bid >> 3) * 32, ksg = bid & 7;
            stage_mm(g_htT, g_htT, 1<<30, ksg*128, ksg*128 + 128, proj_W, 512, nc,
                     As, Ws, red);
            part_epi(red, g_oePart + (long)ksg*(Ee*Bb) + nc*32);
        }
        gbar(tgt);

        // reduce -> outemb row-major [t*32+b][512]
        if (bid < 64) {
            int id = bid*256 + tid;
            int n = id >> 5, b = id & 31;
            float s = proj_b[n];
            #pragma unroll
            for (int s8 = 0; s8 < 8; s8++) s += g_oePart[(long)s8*(Ee*Bb) + id];
            g_outemb[((long)t*Bb + b)*Ee + n] = s;
        }
        gbar(tgt);
    }
}

// ---------------- vocab GEMM with exp() epilogue ----------------
__global__ void __launch_bounds__(256) gemm_logits(const float* __restrict__ A,
                                                   const float* __restrict__ Bw,
                                                   const float* __restrict__ bias,
                                                   float* __restrict__ E) {
    __shared__ float As[16][64];
    __shared__ float Bs[16][64];
    int tid = threadIdx.x;
    int bn = blockIdx.x * 64;
    int bm = blockIdx.y * 64;
    int tx = tid & 15, ty = tid >> 4;
    int arow = tid >> 2, akq = tid & 3;
    int brow = tid >> 4, bcq = tid & 15;
    u64 acc2[4][2] = {};
    for (int k0 = 0; k0 < 512; k0 += 16) {
        float4 av = *(const float4*)(A + (long)(bm+arow)*Ee + k0 + akq*4);
        As[akq*4+0][arow]=av.x; As[akq*4+1][arow]=av.y;
        As[akq*4+2][arow]=av.z; As[akq*4+3][arow]=av.w;
        float4 bv = *(const float4*)(Bw + (long)(k0+brow)*VTv + bn + bcq*4);
        *(float4*)&Bs[brow][bcq*4] = bv;
        __syncthreads();
        #pragma unroll
        for (int kk = 0; kk < 16; kk++) {
            float4 a4 = *(const float4*)&As[kk][ty*4];
            ulonglong2 b2 = *(const ulonglong2*)&Bs[kk][tx*4];
            u64 aa;
            aa = pk2(a4.x, a4.x); fma2(acc2[0][0], aa, b2.x); fma2(acc2[0][1], aa, b2.y);
            aa = pk2(a4.y, a4.y); fma2(acc2[1][0], aa, b2.x); fma2(acc2[1][1], aa, b2.y);
            aa = pk2(a4.z, a4.z); fma2(acc2[2][0], aa, b2.x); fma2(acc2[2][1], aa, b2.y);
            aa = pk2(a4.w, a4.w); fma2(acc2[3][0], aa, b2.x); fma2(acc2[3][1], aa, b2.y);
        }
        __syncthreads();
    }
    #pragma unroll
    for (int i = 0; i < 4; i++) {
        float* erow = E + (size_t)(bm+ty*4+i)*VTv + bn + tx*4;
        float2 c01 = up2(acc2[i][0]), c23 = up2(acc2[i][1]);
        erow[0] = expf(c01.x + bias[bn+tx*4+0]);
        erow[1] = expf(c01.y + bias[bn+tx*4+1]);
        erow[2] = expf(c23.x + bias[bn+tx*4+2]);
        erow[3] = expf(c23.y + bias[bn+tx*4+3]);
    }
}

// ---------------- normalize + layout remap ----------------
__global__ void softmax_norm(const float* __restrict__ E, float* __restrict__ out) {
    int m = blockIdx.x;                      // m = t*32 + b
    const float* er = E + (size_t)m*VTv;
    int tid = threadIdx.x;
    __shared__ float red[256];
    float sum = 0.f;
    for (int i = tid; i < VTv; i += 256) sum += er[i];
    red[tid] = sum; __syncthreads();
    for (int s = 128; s; s >>= 1) { if (tid < s) red[tid] += red[tid+s]; __syncthreads(); }
    float inv = 1.f/red[0];
    int t = m >> 5, b = m & 31;
    float* orow = out + (size_t)(b*Tt + t)*VTv;
    for (int i = tid; i < VTv; i += 256) orow[i] = er[i]*inv;
}

// ---------------- host ----------------
extern "C" void kernel_launch(void* const* d_in, const int* in_sizes, int n_in,
                              void* d_out, int out_size) {
    const int*   src    = (const int*)d_in[0];
    const int*   tgt    = (const int*)d_in[1];
    const float* s_emb  = (const float*)d_in[2];
    const float* s_pW   = (const float*)d_in[3];
    const float* s_pb   = (const float*)d_in[4];
    const float* t_emb  = (const float*)d_in[5];
    const float* t_pW   = (const float*)d_in[6];
    const float* t_pb   = (const float*)d_in[7];
    const float* enc_W  = (const float*)d_in[8];
    const float* enc_b  = (const float*)d_in[9];
    const float* dec_W  = (const float*)d_in[10];
    const float* dec_b  = (const float*)d_in[11];
    const float* W_c    = (const float*)d_in[12];
    const float* b_c    = (const float*)d_in[13];
    const float* proj_W = (const float*)d_in[14];
    const float* proj_b = (const float*)d_in[15];
    const float* proj_Wo= (const float*)d_in[16];
    const float* proj_bo= (const float*)d_in[17];
    float* out = (float*)d_out;

    float *srcX,*tgtX,*Wre,*Wrd,*bre,*brd,*zxe,*zxd,*outemb,*elog;
    cudaGetSymbolAddress((void**)&srcX,   g_srcX);
    cudaGetSymbolAddress((void**)&tgtX,   g_tgtX);
    cudaGetSymbolAddress((void**)&Wre,    g_Wre);
    cudaGetSymbolAddress((void**)&Wrd,    g_Wrd);
    cudaGetSymbolAddress((void**)&bre,    g_bre);
    cudaGetSymbolAddress((void**)&brd,    g_brd);
    cudaGetSymbolAddress((void**)&zxe,    g_zxe);
    cudaGetSymbolAddress((void**)&zxd,    g_zxd);
    cudaGetSymbolAddress((void**)&outemb, g_outemb);
    cudaGetSymbolAddress((void**)&elog,   g_elog);

    cudaFuncSetAttribute(seq_kernel, cudaFuncAttributeMaxDynamicSharedMemorySize, SMEM_SEQ);
    cudaFuncSetAttribute(xgate,      cudaFuncAttributeMaxDynamicSharedMemorySize, SMEM_XG);

    zero_state<<<(HB+255)/256, 256>>>();
    reorder_W<<<1024, 256>>>(enc_W, enc_b, Wre, bre);
    reorder_W<<<1024, 256>>>(dec_W, dec_b, Wrd, brd);
    embed_proj<<<dim3(32,64), 256>>>(src, s_emb, (const float4*)s_pW, (const float4*)s_pb, srcX);
    embed_proj<<<dim3(32,64), 256>>>(tgt, t_emb, (const float4*)t_pW, (const float4*)t_pb, tgtX);

    // x-part gate pre-activations for all timesteps (layer 0 of each stack)
    xgate<<<dim3(128,Tt), 256, SMEM_XG>>>(srcX, Wre, zxe);
    xgate<<<dim3(128,Tt), 256, SMEM_XG>>>(tgtX, Wrd, zxd);

    // full recurrent encoder+decoder in one persistent kernel
    seq_kernel<<<NBLK, 256, SMEM_SEQ>>>(W_c, b_c, proj_W, proj_b);

    // vocab projection (+exp) and normalization
    gemm_logits<<<dim3(VTv/64, (Tt*Bb)/64), 256>>>(outemb, proj_Wo, proj_bo, elog);
    softmax_norm<<<Tt*Bb, 256>>>(elog, out);
}